// round 8
// baseline (speedup 1.0000x reference)
#include <cuda_runtime.h>
#include <stdint.h>

// ---------------- constants ----------------
#define EPSc   0.05f
#define DTc    0.1f
#define RMINc  1.0e5f
#define RMAXc  1.0e7f
#define CMINc  1.0e-7f
#define CMAXc  1.0e-4f

// ---------------- device scratch (static: no allocation allowed) ----------------
__device__ float g_w1p  [4*34*32];        // [n][m][o]   raw noisy theta1 (m=32 bias, m=33 zeros-row)
__device__ float g_w2p  [4*1058*64];      // [n][j][2*o] raw noisy theta2, duplicated + K-permuted
                                          //   j<1024: filter rows, 1024+c: raw-a1 rows,
                                          //   1056: bias row, 1057: denominator-only row
__device__ float g_a1T  [4*32*256*32];    // [n][c][t][b]
__device__ float g_beta [2*256*1024*4];   // [bank][t][k][n]
__device__ float g_s0   [2*1024*4*32];    // [bank][k][n][b]
__device__ float g_yout [4*1024*256*32];  // [n][k][t][b]   (128 MB)

// ---------------- packed f32x2 FMA ----------------
#define FMA2(d, a, b, c) \
    asm("fma.rn.f32x2 %0, %1, %2, %3;" : "=l"(d) : "l"(a), "l"(b), "l"(c))

// ---------------- JAX threefry2x32 (partitionable semantics) ----------------
__device__ __forceinline__ uint2 tf2x32_d(uint32_t k0, uint32_t k1, uint32_t c0, uint32_t c1) {
    uint32_t ks2 = k0 ^ k1 ^ 0x1BD11BDAu;
    uint32_t x0 = c0 + k0, x1 = c1 + k1;
#define TFR(r) { x0 += x1; x1 = __funnelshift_l(x1, x1, (r)); x1 ^= x0; }
    TFR(13) TFR(15) TFR(26) TFR(6)   x0 += k1;  x1 += ks2 + 1u;
    TFR(17) TFR(29) TFR(16) TFR(24)  x0 += ks2; x1 += k0  + 2u;
    TFR(13) TFR(15) TFR(26) TFR(6)   x0 += k0;  x1 += k1  + 3u;
    TFR(17) TFR(29) TFR(16) TFR(24)  x0 += k1;  x1 += ks2 + 4u;
    TFR(13) TFR(15) TFR(26) TFR(6)   x0 += ks2; x1 += k0  + 5u;
#undef TFR
    return make_uint2(x0, x1);
}

__device__ __forceinline__ float u01p(uint2 key, uint32_t idx) {
    uint2 v = tf2x32_d(key.x, key.y, 0u, idx);
    uint32_t u = v.x ^ v.y;
    return __uint_as_float((u >> 9) | 0x3f800000u) - 1.0f;
}

struct Keys {
    uint2 kth1, kth2;          // theta noise keys
    uint2 r1, c1, m1;          // bank1 nR, nC, mu
    uint2 r2, c2, m2;          // bank2
    uint2 s01, s02;            // initial states
};

// ---------------- kernel: ALL RNG work in one launch ----------------
// ranges: [0,4352) thn1 | [4352,139776) thn2 | [139776,2236928) beta | rest s0
__global__ void __launch_bounds__(256) k_rng(Keys K, const float* __restrict__ th1,
                                             const float* __restrict__ th2,
                                             const float* __restrict__ Rlf,
                                             const float* __restrict__ Clf) {
    int gi = blockIdx.x * blockDim.x + threadIdx.x;
    if (gi < 4352) {
        // theta1 noise: shape (4, 34, 32), idx = (n*34+m)*32+o
        int i = gi;
        int o = i & 31; int nm = i >> 5; int m = nm % 34;
        float u = u01p(K.kth1, (uint32_t)i);
        float noise = (u * 2.0f - 1.0f) * EPSc + 1.0f;
        float t = th1[m*32 + o];
        t = fminf(fmaxf(t, -10.0f), 10.0f);
        if (fabsf(t) < 0.01f) t = 0.0f;
        g_w1p[i] = t * noise;                 // same [n][m][o] layout as idx
    } else if (gi < 139776) {
        // theta2 noise: shape (4, 1058, 32), idx = (n*1058+m)*32+o
        int i = gi - 4352;
        int o = i & 31; int nm = i >> 5; int m = nm % 1058; int n = nm / 1058;
        float u = u01p(K.kth2, (uint32_t)i);
        float noise = (u * 2.0f - 1.0f) * EPSc + 1.0f;
        float t = th2[m*32 + o];
        t = fminf(fmaxf(t, -10.0f), 10.0f);
        if (fabsf(t) < 0.01f) t = 0.0f;
        float v = t * noise;
        int j;
        if (m >= 1056) j = m;                 // 1056 bias, 1057 denom-only
        else {
            int c = m / 33, g = m % 33;
            j = (g == 0) ? (1024 + c) : (c*32 + g - 1);
        }
        g_w2p[(n*1058 + j)*64 + 2*o    ] = v;
        g_w2p[(n*1058 + j)*64 + 2*o + 1] = v;
    } else if (gi < 2236928) {
        // beta: per-bank element idx e over shape (256,1024,4)
        int i = gi - 139776;
        int bank = i >> 20;
        uint32_t e = (uint32_t)(i & 1048575);
        int k = (int)((e >> 2) & 1023u);
        int bn = (int)(e & 3u);
        uint2 kR = bank ? K.r2 : K.r1;
        uint2 kC = bank ? K.c2 : K.c1;
        uint2 km = bank ? K.m2 : K.m1;
        float nR = (u01p(kR, e) * 2.0f - 1.0f) * EPSc + 1.0f;
        float nC = (u01p(kC, e) * 2.0f - 1.0f) * EPSc + 1.0f;
        float mu =  u01p(km, e) * 0.2f + 1.0f;
        float Rr = Rlf[k*2 + bank], Cr = Clf[k*2 + bank];
        float Rt = (1.0f / (1.0f + expf(-Rr))) * (RMAXc - RMINc) + RMINc;
        float Ct = (1.0f / (1.0f + expf(-Cr))) * (CMAXc - CMINc) + CMINc;
        float RC = mu * (Rt * nR) * (Ct * nC);
        (void)bn;
        g_beta[i] = RC / (RC + DTc);
    } else if (gi < 2499072) {
        // s0: shape (1024,4,32) per bank
        int i = gi - 2236928;
        int bank = i >> 17;
        uint32_t e = (uint32_t)(i & 131071);
        g_s0[i] = u01p(bank ? K.s02 : K.s01, e);
    }
}

// ---------------- kernel: pmac1 (x -> a1T), self-normalizing ----------------
// grid (32 t-chunks, 4 n), 256 threads = 8 t x 32 b
__global__ void __launch_bounds__(256) k_pmac1(const float* __restrict__ x) {
    int n = blockIdx.y;
    int tc = blockIdx.x;
    int tid = threadIdx.x;
    int tl = tid & 7, b = tid >> 3;
    int t = tc*8 + tl;
    __shared__ float w[34*32];
    __shared__ float invs[32];
    __shared__ float osm[8][8][33];
    for (int i = tid; i < 34*32; i += 256) w[i] = g_w1p[n*34*32 + i];
    __syncthreads();
    if (tid < 32) {
        float s = 0.0f;
        #pragma unroll
        for (int m = 0; m < 34; m++) s += fabsf(w[m*32 + tid]);
        invs[tid] = 1.0f / (s + 1e-10f);
    }
    __syncthreads();
    const float* xp = x + ((size_t)(n*32 + b)*32)*256 + t;
    float acc[32];
    const float4* wb4 = (const float4*)&w[32*32];       // raw bias row
    #pragma unroll
    for (int o4 = 0; o4 < 8; o4++) {
        float4 v = wb4[o4];
        acc[4*o4+0]=v.x; acc[4*o4+1]=v.y; acc[4*o4+2]=v.z; acc[4*o4+3]=v.w;
    }
    #pragma unroll 4
    for (int m = 0; m < 32; m++) {
        float xv = xp[(size_t)m*256];
        const float4* wr = (const float4*)&w[m*32];
        #pragma unroll
        for (int o4 = 0; o4 < 8; o4++) {
            float4 v = wr[o4];
            acc[4*o4+0]=fmaf(xv,v.x,acc[4*o4+0]); acc[4*o4+1]=fmaf(xv,v.y,acc[4*o4+1]);
            acc[4*o4+2]=fmaf(xv,v.z,acc[4*o4+2]); acc[4*o4+3]=fmaf(xv,v.w,acc[4*o4+3]);
        }
    }
    // activation + transposed (coalesced) store of a1T[n][o][t][b]
    for (int og = 0; og < 4; og++) {
        __syncthreads();
        #pragma unroll
        for (int oo = 0; oo < 8; oo++) {
            int o = og*8 + oo;
            osm[oo][tl][b] = 0.05f + 0.5f * tanhf((acc[o]*invs[o] - 0.3f) * 3.0f);
        }
        __syncthreads();
        int b_r = tid & 31, hi = tid >> 5;
        #pragma unroll
        for (int j = 0; j < 8; j++) {
            g_a1T[((size_t)(n*32 + og*8 + hi)*256 + tc*8 + j)*32 + b_r] = osm[hi][j][b_r];
        }
    }
}

// ---------------- kernel: fused two-bank scan ----------------
// grid 256 = (n 4, c 32, fh 2); 512 threads = 16 f x 32 b
__global__ void __launch_bounds__(512) k_scan() {
    int bi = blockIdx.x;
    int n = bi & 3, c = (bi >> 2) & 31, fh = bi >> 7;
    int f = fh*16 + (threadIdx.x >> 5), b = threadIdx.x & 31;
    int k = c*32 + f;
    float s = g_s0[(k*4 + n)*32 + b];
    float r = g_s0[131072 + (k*4 + n)*32 + b];
    const float* xp  = &g_a1T[((size_t)(n*32 + c)*256) * 32 + b];   // +t*32
    const float* b1p = &g_beta[(k*4 + n)];                          // +t*4096
    const float* b2p = b1p + 1048576;
    float* yp = &g_yout[((size_t)(n*1024 + k)*256) * 32 + b];       // +t*32
    #pragma unroll 4
    for (int t = 0; t < 256; t++) {
        float be1 = __ldg(b1p + (size_t)t*4096);
        float be2 = __ldg(b2p + (size_t)t*4096);
        float xv  = xp[t*32];
        yp[t*32] = r;                      // scan emits the PRE-update carry
        r = be2 * r + (1.0f - be2) * s;    // bank2 consumes y1[t] = current s
        s = be1 * s + (1.0f - be1) * xv;   // bank1 update
    }
}

// ---------------- kernel: pmac2 as register-tiled GEMM (f32x2), self-norm ----
// Per n: out[8192 m, 32 o] = act( inv[o] * (h[8192,1056]*Wraw + bias_raw) ).
// Block: 256-row M tile, full N=32. Thread: 8 rows x 4 cols via 16 FFMA2/k.
// 2-stage cp.async pipeline, K-chunk 16 (R5-best config).
__global__ void __launch_bounds__(256) k_pmac2(float* __restrict__ out) {
    const int n  = blockIdx.y;
    const int M0 = blockIdx.x * 256;
    const int tid = threadIdx.x;
    const int cg = tid & 7;        // col group: o = cg*4 + c
    const int rg = tid >> 3;       // row group: m = M0 + rg*8 + rr
    __shared__ float hs[2][16][256];
    __shared__ float wd[2][16][64];
    __shared__ float psum[8][32];
    __shared__ float inv_sm[32];
    const float* ybase = g_yout + (size_t)n*1024*8192 + M0;   // + j*8192
    const float* abase = g_a1T  + (size_t)n*32*8192   + M0;   // + (j-1024)*8192
    const float* wbase = g_w2p  + (size_t)n*1058*64;          // + j*64

    // --- column denominators: sum |w| over ALL 1058 rows (incl. zeros-row 1057)
    {
        int o = tid & 31, p = tid >> 5;                       // 8 parts x 32 o
        float s = 0.0f;
        for (int j = p; j < 1058; j += 8) s += fabsf(wbase[(size_t)j*64 + 2*o]);
        psum[p][o] = s;
    }
    __syncthreads();
    if (tid < 32) {
        float s = 0.0f;
        #pragma unroll
        for (int p = 0; p < 8; p++) s += psum[p][tid];
        inv_sm[tid] = 1.0f / (s + 1e-10f);
    }

    unsigned long long acc[4][4];
    {
        const unsigned long long* bp =
            (const unsigned long long*)(wbase + 1056*64 + cg*8);   // raw bias
        #pragma unroll
        for (int cc = 0; cc < 4; cc++) {
            unsigned long long bv = bp[cc];
            #pragma unroll
            for (int rp = 0; rp < 4; rp++) acc[rp][cc] = bv;
        }
    }

    auto load_stage = [&](int s, int buf) {
        int k0 = s * 16;
        #pragma unroll
        for (int j = 0; j < 4; j++) {
            int ch = tid + 256*j;
            int kk = ch >> 6, f4 = ch & 63;
            int jg = k0 + kk;
            const float* src = (jg < 1024)
                ? (ybase + (size_t)jg*8192 + f4*4)
                : (abase + (size_t)(jg - 1024)*8192 + f4*4);
            unsigned dst = (unsigned)__cvta_generic_to_shared(&hs[buf][kk][f4*4]);
            asm volatile("cp.async.cg.shared.global [%0], [%1], 16;" :: "r"(dst), "l"(src));
        }
        {
            int kk = tid >> 4, f4 = tid & 15;
            const float* src = wbase + (size_t)(k0 + kk)*64 + f4*4;
            unsigned dst = (unsigned)__cvta_generic_to_shared(&wd[buf][kk][f4*4]);
            asm volatile("cp.async.cg.shared.global [%0], [%1], 16;" :: "r"(dst), "l"(src));
        }
        asm volatile("cp.async.commit_group;");
    };

    load_stage(0, 0);
    for (int s = 0; s < 66; s++) {
        int buf = s & 1;
        if (s < 65) { load_stage(s + 1, buf ^ 1); asm volatile("cp.async.wait_group 1;"); }
        else        { asm volatile("cp.async.wait_group 0;"); }
        __syncthreads();
        #pragma unroll
        for (int kk = 0; kk < 16; kk++) {
            ulonglong2 hA = *(const ulonglong2*)(&hs[buf][kk][rg*8]);
            ulonglong2 hB = *(const ulonglong2*)(&hs[buf][kk][rg*8 + 4]);
            ulonglong2 wA = *(const ulonglong2*)(&wd[buf][kk][cg*8]);
            ulonglong2 wB = *(const ulonglong2*)(&wd[buf][kk][cg*8 + 4]);
            unsigned long long h[4]  = { hA.x, hA.y, hB.x, hB.y };
            unsigned long long wv[4] = { wA.x, wA.y, wB.x, wB.y };
            #pragma unroll
            for (int rp = 0; rp < 4; rp++) {
                #pragma unroll
                for (int cc = 0; cc < 4; cc++)
                    FMA2(acc[rp][cc], h[rp], wv[cc], acc[rp][cc]);
            }
        }
        __syncthreads();
    }

    // epilogue: normalize + activation + store (out[n][b][o][t])
    #pragma unroll
    for (int rp = 0; rp < 4; rp++) {
        int m0 = M0 + rg*8 + rp*2;            // even; m0 and m0+1 share t
        int t = m0 >> 5, b = m0 & 31;
        float* op0 = out + ((size_t)(n*32 + b)*32)*256 + t;
        #pragma unroll
        for (int cc = 0; cc < 4; cc++) {
            int o = cg*4 + cc;
            float sc = inv_sm[o];
            float lo = __uint_as_float((unsigned)(acc[rp][cc] & 0xffffffffu));
            float hi = __uint_as_float((unsigned)(acc[rp][cc] >> 32));
            lo = 0.05f + 0.5f * tanhf((lo*sc - 0.3f) * 3.0f);
            hi = 0.05f + 0.5f * tanhf((hi*sc - 0.3f) * 3.0f);
            op0[(size_t)o*256]        = lo;     // row m0   (b)
            op0[8192 + (size_t)o*256] = hi;     // row m0+1 (b+1)
        }
    }
}

// ---------------- host threefry (derive subkeys) ----------------
static inline uint32_t rotl32(uint32_t x, int r) { return (x << r) | (x >> (32 - r)); }
static void tf_host(uint32_t k0, uint32_t k1, uint32_t c0, uint32_t c1,
                    uint32_t* o0, uint32_t* o1) {
    uint32_t ks[3] = { k0, k1, k0 ^ k1 ^ 0x1BD11BDAu };
    const int R[2][4] = { {13,15,26,6}, {17,29,16,24} };
    uint32_t x0 = c0 + k0, x1 = c1 + k1;
    for (int i = 0; i < 5; i++) {
        for (int j = 0; j < 4; j++) { x0 += x1; x1 = rotl32(x1, R[i & 1][j]); x1 ^= x0; }
        x0 += ks[(i + 1) % 3];
        x1 += ks[(i + 2) % 3] + (uint32_t)(i + 1);
    }
    *o0 = x0; *o1 = x1;
}

extern "C" void kernel_launch(void* const* d_in, const int* in_sizes, int n_in,
                              void* d_out, int out_size) {
    const float* x   = (const float*)d_in[0];
    const float* th1 = (const float*)d_in[1];
    const float* th2 = (const float*)d_in[2];
    const float* Rlf = (const float*)d_in[3];
    const float* Clf = (const float*)d_in[4];
    float* out = (float*)d_out;

    // key(42) = (0,42); split(key,4) -> k1..k4 (partitionable)
    uint2 kk[4];
    for (uint32_t i = 0; i < 4; i++) tf_host(0u, 42u, 0u, i, &kk[i].x, &kk[i].y);
    uint2 b1[4], b2[4];
    for (uint32_t i = 0; i < 4; i++) {
        tf_host(kk[1].x, kk[1].y, 0u, i, &b1[i].x, &b1[i].y);
        tf_host(kk[2].x, kk[2].y, 0u, i, &b2[i].x, &b2[i].y);
    }
    Keys K;
    K.kth1 = kk[0]; K.kth2 = kk[3];
    K.r1 = b1[0]; K.c1 = b1[1]; K.m1 = b1[2]; K.s01 = b1[3];
    K.r2 = b2[0]; K.c2 = b2[1]; K.m2 = b2[2]; K.s02 = b2[3];

    k_rng  <<< (2499072 + 255)/256, 256 >>> (K, th1, th2, Rlf, Clf);
    k_pmac1<<< dim3(32, 4), 256 >>> (x);
    k_scan <<< 256, 512 >>> ();
    k_pmac2<<< dim3(32, 4), 256 >>> (out);
}

// round 9
// speedup vs baseline: 1.0690x; 1.0690x over previous
#include <cuda_runtime.h>
#include <stdint.h>

// ---------------- constants ----------------
#define EPSc   0.05f
#define DTc    0.1f
#define RMINc  1.0e5f
#define RMAXc  1.0e7f
#define CMINc  1.0e-7f
#define CMAXc  1.0e-4f

// ---------------- device scratch (static: no allocation allowed) ----------------
__device__ float g_w1p  [4*34*32];        // [n][m][o]   raw noisy theta1 (m=32 bias, m=33 zeros-row)
__device__ float g_w2p  [4*1058*64];      // [n][j][2*o] raw noisy theta2, duplicated + K-permuted
                                          //   j<1024: filter rows, 1024+c: raw-a1 rows,
                                          //   1056: bias row, 1057: denominator-only row
__device__ float g_a1T  [4*32*256*32];    // [n][c][t][b]
__device__ float g_beta [2*256*1024*4];   // [bank][t][k][n]
__device__ float g_s0   [2*1024*4*32];    // [bank][k][n][b]
__device__ float g_yout [4*1024*256*32];  // [n][k][t][b]   (128 MB)
__device__ float g_part [3*4*8192*32];    // [slice][n][m][o]  split-K partials (12.6 MB)

// ---------------- packed f32x2 FMA ----------------
#define FMA2(d, a, b, c) \
    asm("fma.rn.f32x2 %0, %1, %2, %3;" : "=l"(d) : "l"(a), "l"(b), "l"(c))

// ---------------- JAX threefry2x32 (partitionable semantics) ----------------
__device__ __forceinline__ uint2 tf2x32_d(uint32_t k0, uint32_t k1, uint32_t c0, uint32_t c1) {
    uint32_t ks2 = k0 ^ k1 ^ 0x1BD11BDAu;
    uint32_t x0 = c0 + k0, x1 = c1 + k1;
#define TFR(r) { x0 += x1; x1 = __funnelshift_l(x1, x1, (r)); x1 ^= x0; }
    TFR(13) TFR(15) TFR(26) TFR(6)   x0 += k1;  x1 += ks2 + 1u;
    TFR(17) TFR(29) TFR(16) TFR(24)  x0 += ks2; x1 += k0  + 2u;
    TFR(13) TFR(15) TFR(26) TFR(6)   x0 += k0;  x1 += k1  + 3u;
    TFR(17) TFR(29) TFR(16) TFR(24)  x0 += k1;  x1 += ks2 + 4u;
    TFR(13) TFR(15) TFR(26) TFR(6)   x0 += ks2; x1 += k0  + 5u;
#undef TFR
    return make_uint2(x0, x1);
}

__device__ __forceinline__ float u01p(uint2 key, uint32_t idx) {
    uint2 v = tf2x32_d(key.x, key.y, 0u, idx);
    uint32_t u = v.x ^ v.y;
    return __uint_as_float((u >> 9) | 0x3f800000u) - 1.0f;
}

struct Keys {
    uint2 kth1, kth2;          // theta noise keys
    uint2 r1, c1, m1;          // bank1 nR, nC, mu
    uint2 r2, c2, m2;          // bank2
    uint2 s01, s02;            // initial states
};

// ---------------- kernel: ALL RNG work in one launch ----------------
// ranges: [0,4352) thn1 | [4352,139776) thn2 | [139776,2236928) beta | rest s0
__global__ void __launch_bounds__(256) k_rng(Keys K, const float* __restrict__ th1,
                                             const float* __restrict__ th2,
                                             const float* __restrict__ Rlf,
                                             const float* __restrict__ Clf) {
    int gi = blockIdx.x * blockDim.x + threadIdx.x;
    if (gi < 4352) {
        // theta1 noise: shape (4, 34, 32), idx = (n*34+m)*32+o
        int i = gi;
        int o = i & 31; int nm = i >> 5; int m = nm % 34;
        float u = u01p(K.kth1, (uint32_t)i);
        float noise = (u * 2.0f - 1.0f) * EPSc + 1.0f;
        float t = th1[m*32 + o];
        t = fminf(fmaxf(t, -10.0f), 10.0f);
        if (fabsf(t) < 0.01f) t = 0.0f;
        g_w1p[i] = t * noise;                 // same [n][m][o] layout as idx
    } else if (gi < 139776) {
        // theta2 noise: shape (4, 1058, 32), idx = (n*1058+m)*32+o
        int i = gi - 4352;
        int o = i & 31; int nm = i >> 5; int m = nm % 1058; int n = nm / 1058;
        float u = u01p(K.kth2, (uint32_t)i);
        float noise = (u * 2.0f - 1.0f) * EPSc + 1.0f;
        float t = th2[m*32 + o];
        t = fminf(fmaxf(t, -10.0f), 10.0f);
        if (fabsf(t) < 0.01f) t = 0.0f;
        float v = t * noise;
        int j;
        if (m >= 1056) j = m;                 // 1056 bias, 1057 denom-only
        else {
            int c = m / 33, g = m % 33;
            j = (g == 0) ? (1024 + c) : (c*32 + g - 1);
        }
        g_w2p[(n*1058 + j)*64 + 2*o    ] = v;
        g_w2p[(n*1058 + j)*64 + 2*o + 1] = v;
    } else if (gi < 2236928) {
        // beta: per-bank element idx e over shape (256,1024,4)
        int i = gi - 139776;
        int bank = i >> 20;
        uint32_t e = (uint32_t)(i & 1048575);
        int k = (int)((e >> 2) & 1023u);
        uint2 kR = bank ? K.r2 : K.r1;
        uint2 kC = bank ? K.c2 : K.c1;
        uint2 km = bank ? K.m2 : K.m1;
        float nR = (u01p(kR, e) * 2.0f - 1.0f) * EPSc + 1.0f;
        float nC = (u01p(kC, e) * 2.0f - 1.0f) * EPSc + 1.0f;
        float mu =  u01p(km, e) * 0.2f + 1.0f;
        float Rr = Rlf[k*2 + bank], Cr = Clf[k*2 + bank];
        float Rt = (1.0f / (1.0f + expf(-Rr))) * (RMAXc - RMINc) + RMINc;
        float Ct = (1.0f / (1.0f + expf(-Cr))) * (CMAXc - CMINc) + CMINc;
        float RC = mu * (Rt * nR) * (Ct * nC);
        g_beta[i] = RC / (RC + DTc);
    } else if (gi < 2499072) {
        // s0: shape (1024,4,32) per bank
        int i = gi - 2236928;
        int bank = i >> 17;
        uint32_t e = (uint32_t)(i & 131071);
        g_s0[i] = u01p(bank ? K.s02 : K.s01, e);
    }
}

// ---------------- kernel: pmac1 (x -> a1T), self-normalizing ----------------
// grid (32 t-chunks, 4 n), 256 threads = 8 t x 32 b
__global__ void __launch_bounds__(256) k_pmac1(const float* __restrict__ x) {
    int n = blockIdx.y;
    int tc = blockIdx.x;
    int tid = threadIdx.x;
    int tl = tid & 7, b = tid >> 3;
    int t = tc*8 + tl;
    __shared__ float w[34*32];
    __shared__ float invs[32];
    __shared__ float osm[8][8][33];
    for (int i = tid; i < 34*32; i += 256) w[i] = g_w1p[n*34*32 + i];
    __syncthreads();
    if (tid < 32) {
        float s = 0.0f;
        #pragma unroll
        for (int m = 0; m < 34; m++) s += fabsf(w[m*32 + tid]);
        invs[tid] = 1.0f / (s + 1e-10f);
    }
    __syncthreads();
    const float* xp = x + ((size_t)(n*32 + b)*32)*256 + t;
    float acc[32];
    const float4* wb4 = (const float4*)&w[32*32];       // raw bias row
    #pragma unroll
    for (int o4 = 0; o4 < 8; o4++) {
        float4 v = wb4[o4];
        acc[4*o4+0]=v.x; acc[4*o4+1]=v.y; acc[4*o4+2]=v.z; acc[4*o4+3]=v.w;
    }
    #pragma unroll 4
    for (int m = 0; m < 32; m++) {
        float xv = xp[(size_t)m*256];
        const float4* wr = (const float4*)&w[m*32];
        #pragma unroll
        for (int o4 = 0; o4 < 8; o4++) {
            float4 v = wr[o4];
            acc[4*o4+0]=fmaf(xv,v.x,acc[4*o4+0]); acc[4*o4+1]=fmaf(xv,v.y,acc[4*o4+1]);
            acc[4*o4+2]=fmaf(xv,v.z,acc[4*o4+2]); acc[4*o4+3]=fmaf(xv,v.w,acc[4*o4+3]);
        }
    }
    // activation + transposed (coalesced) store of a1T[n][o][t][b]
    for (int og = 0; og < 4; og++) {
        __syncthreads();
        #pragma unroll
        for (int oo = 0; oo < 8; oo++) {
            int o = og*8 + oo;
            osm[oo][tl][b] = 0.05f + 0.5f * tanhf((acc[o]*invs[o] - 0.3f) * 3.0f);
        }
        __syncthreads();
        int b_r = tid & 31, hi = tid >> 5;
        #pragma unroll
        for (int j = 0; j < 8; j++) {
            g_a1T[((size_t)(n*32 + og*8 + hi)*256 + tc*8 + j)*32 + b_r] = osm[hi][j][b_r];
        }
    }
}

// ---------------- kernel: fused two-bank scan ----------------
// grid 256 = (n 4, c 32, fh 2); 512 threads = 16 f x 32 b
__global__ void __launch_bounds__(512) k_scan() {
    int bi = blockIdx.x;
    int n = bi & 3, c = (bi >> 2) & 31, fh = bi >> 7;
    int f = fh*16 + (threadIdx.x >> 5), b = threadIdx.x & 31;
    int k = c*32 + f;
    float s = g_s0[(k*4 + n)*32 + b];
    float r = g_s0[131072 + (k*4 + n)*32 + b];
    const float* xp  = &g_a1T[((size_t)(n*32 + c)*256) * 32 + b];   // +t*32
    const float* b1p = &g_beta[(k*4 + n)];                          // +t*4096
    const float* b2p = b1p + 1048576;
    float* yp = &g_yout[((size_t)(n*1024 + k)*256) * 32 + b];       // +t*32
    #pragma unroll 4
    for (int t = 0; t < 256; t++) {
        float be1 = __ldg(b1p + (size_t)t*4096);
        float be2 = __ldg(b2p + (size_t)t*4096);
        float xv  = xp[t*32];
        yp[t*32] = r;                      // scan emits the PRE-update carry
        r = be2 * r + (1.0f - be2) * s;    // bank2 consumes y1[t] = current s
        s = be1 * s + (1.0f - be1) * xv;   // bank1 update
    }
}

// ---------------- kernel: pmac2 GEMM, split-K x 3 ----------------
// Per (n, slice): partial[m, o] = sum over 352 K-rows of h * Wraw.
// Block: 256-row M tile, full N=32. Thread: 8 rows x 4 cols via 16 FFMA2/k.
// 2-stage cp.async pipeline, K-chunk 16, 22 stages per slice.
__global__ void __launch_bounds__(256) k_pmac2() {
    const int n  = blockIdx.y;
    const int sl = blockIdx.z;               // K slice 0..2
    const int M0 = blockIdx.x * 256;
    const int j0 = sl * 352;
    const int tid = threadIdx.x;
    const int cg = tid & 7;        // col group: o = cg*4 + c
    const int rg = tid >> 3;       // row group: m = M0 + rg*8 + rr
    __shared__ float hs[2][16][256];
    __shared__ float wd[2][16][64];
    const float* ybase = g_yout + (size_t)n*1024*8192 + M0;   // + j*8192
    const float* abase = g_a1T  + (size_t)n*32*8192   + M0;   // + (j-1024)*8192
    const float* wbase = g_w2p  + (size_t)n*1058*64;          // + j*64

    unsigned long long acc[4][4];
    #pragma unroll
    for (int rp = 0; rp < 4; rp++)
        #pragma unroll
        for (int cc = 0; cc < 4; cc++) acc[rp][cc] = 0ull;

    auto load_stage = [&](int s, int buf) {
        int k0 = j0 + s * 16;
        #pragma unroll
        for (int j = 0; j < 4; j++) {
            int ch = tid + 256*j;
            int kk = ch >> 6, f4 = ch & 63;
            int jg = k0 + kk;
            const float* src = (jg < 1024)
                ? (ybase + (size_t)jg*8192 + f4*4)
                : (abase + (size_t)(jg - 1024)*8192 + f4*4);
            unsigned dst = (unsigned)__cvta_generic_to_shared(&hs[buf][kk][f4*4]);
            asm volatile("cp.async.cg.shared.global [%0], [%1], 16;" :: "r"(dst), "l"(src));
        }
        {
            int kk = tid >> 4, f4 = tid & 15;
            const float* src = wbase + (size_t)(k0 + kk)*64 + f4*4;
            unsigned dst = (unsigned)__cvta_generic_to_shared(&wd[buf][kk][f4*4]);
            asm volatile("cp.async.cg.shared.global [%0], [%1], 16;" :: "r"(dst), "l"(src));
        }
        asm volatile("cp.async.commit_group;");
    };

    load_stage(0, 0);
    for (int s = 0; s < 22; s++) {
        int buf = s & 1;
        if (s < 21) { load_stage(s + 1, buf ^ 1); asm volatile("cp.async.wait_group 1;"); }
        else        { asm volatile("cp.async.wait_group 0;"); }
        __syncthreads();
        #pragma unroll
        for (int kk = 0; kk < 16; kk++) {
            ulonglong2 hA = *(const ulonglong2*)(&hs[buf][kk][rg*8]);
            ulonglong2 hB = *(const ulonglong2*)(&hs[buf][kk][rg*8 + 4]);
            ulonglong2 wA = *(const ulonglong2*)(&wd[buf][kk][cg*8]);
            ulonglong2 wB = *(const ulonglong2*)(&wd[buf][kk][cg*8 + 4]);
            unsigned long long h[4]  = { hA.x, hA.y, hB.x, hB.y };
            unsigned long long wv[4] = { wA.x, wA.y, wB.x, wB.y };
            #pragma unroll
            for (int rp = 0; rp < 4; rp++) {
                #pragma unroll
                for (int cc = 0; cc < 4; cc++)
                    FMA2(acc[rp][cc], h[rp], wv[cc], acc[rp][cc]);
            }
        }
        __syncthreads();
    }

    // store partial sums: g_part[sl][n][m][o], float4 over cc (o = cg*4..cg*4+3)
    float* pbase = g_part + ((size_t)(sl*4 + n)*8192) * 32;
    #pragma unroll
    for (int rp = 0; rp < 4; rp++) {
        int m0 = M0 + rg*8 + rp*2;
        float4 lo4, hi4;
        float* l = (float*)&lo4; float* h = (float*)&hi4;
        #pragma unroll
        for (int cc = 0; cc < 4; cc++) {
            l[cc] = __uint_as_float((unsigned)(acc[rp][cc] & 0xffffffffu));
            h[cc] = __uint_as_float((unsigned)(acc[rp][cc] >> 32));
        }
        *(float4*)(pbase + (size_t)m0*32       + cg*4) = lo4;
        *(float4*)(pbase + (size_t)(m0 + 1)*32 + cg*4) = hi4;
    }
}

// ---------------- kernel: epilogue (sum partials + bias, norm, act, store) ----
// grid (32 t-chunks, 4 n), 256 threads. Coalesced reads of g_part, smem
// transpose, near-coalesced float4 writes of out[n][b][o][t].
__global__ void __launch_bounds__(256) k_epi(float* __restrict__ out) {
    const int n  = blockIdx.y;
    const int tc = blockIdx.x;           // 8 t values per block
    const int tid = threadIdx.x;
    __shared__ float res[8][32][33];     // [t_local][b][o] (pad 33)
    __shared__ float psum[8][32];
    __shared__ float inv_sm[32], bias_sm[32];
    const float* wbase = g_w2p + (size_t)n*1058*64;

    // per-column denominator (sum |w| over all 1058 rows) + bias
    {
        int o = tid & 31, p = tid >> 5;
        float s = 0.0f;
        for (int j = p; j < 1058; j += 8) s += fabsf(wbase[(size_t)j*64 + 2*o]);
        psum[p][o] = s;
    }
    __syncthreads();
    if (tid < 32) {
        float s = 0.0f;
        #pragma unroll
        for (int p = 0; p < 8; p++) s += psum[p][tid];
        inv_sm[tid] = 1.0f / (s + 1e-10f);
        bias_sm[tid] = wbase[(size_t)1056*64 + 2*tid];
    }
    __syncthreads();

    const float* p0 = g_part + ((size_t)(0*4 + n)*8192 + tc*256) * 32;
    const float* p1 = g_part + ((size_t)(1*4 + n)*8192 + tc*256) * 32;
    const float* p2 = g_part + ((size_t)(2*4 + n)*8192 + tc*256) * 32;
    for (int i = tid; i < 8192; i += 256) {
        int ml = i >> 5, o = i & 31;
        float z = p0[i] + p1[i] + p2[i] + bias_sm[o];
        res[ml >> 5][ml & 31][o] = 0.05f + 0.5f * tanhf((z*inv_sm[o] - 0.3f) * 3.0f);
    }
    __syncthreads();

    // write out[n][b][o][t]: each thread owns 4 (b,o) pairs, 8 t each (2 float4)
    #pragma unroll
    for (int q = 0; q < 4; q++) {
        int pair = tid + q*256;          // 0..1023 = b*32+o
        int b = pair >> 5, o = pair & 31;
        float4 v0, v1;
        float* v = (float*)&v0;
        #pragma unroll
        for (int j = 0; j < 4; j++) v[j] = res[j][b][o];
        v = (float*)&v1;
        #pragma unroll
        for (int j = 0; j < 4; j++) v[j] = res[4 + j][b][o];
        float* op = out + ((size_t)(n*32 + b)*32 + o)*256 + tc*8;
        *(float4*)op       = v0;
        *(float4*)(op + 4) = v1;
    }
}

// ---------------- host threefry (derive subkeys) ----------------
static inline uint32_t rotl32(uint32_t x, int r) { return (x << r) | (x >> (32 - r)); }
static void tf_host(uint32_t k0, uint32_t k1, uint32_t c0, uint32_t c1,
                    uint32_t* o0, uint32_t* o1) {
    uint32_t ks[3] = { k0, k1, k0 ^ k1 ^ 0x1BD11BDAu };
    const int R[2][4] = { {13,15,26,6}, {17,29,16,24} };
    uint32_t x0 = c0 + k0, x1 = c1 + k1;
    for (int i = 0; i < 5; i++) {
        for (int j = 0; j < 4; j++) { x0 += x1; x1 = rotl32(x1, R[i & 1][j]); x1 ^= x0; }
        x0 += ks[(i + 1) % 3];
        x1 += ks[(i + 2) % 3] + (uint32_t)(i + 1);
    }
    *o0 = x0; *o1 = x1;
}

extern "C" void kernel_launch(void* const* d_in, const int* in_sizes, int n_in,
                              void* d_out, int out_size) {
    const float* x   = (const float*)d_in[0];
    const float* th1 = (const float*)d_in[1];
    const float* th2 = (const float*)d_in[2];
    const float* Rlf = (const float*)d_in[3];
    const float* Clf = (const float*)d_in[4];
    float* out = (float*)d_out;

    // key(42) = (0,42); split(key,4) -> k1..k4 (partitionable)
    uint2 kk[4];
    for (uint32_t i = 0; i < 4; i++) tf_host(0u, 42u, 0u, i, &kk[i].x, &kk[i].y);
    uint2 b1[4], b2[4];
    for (uint32_t i = 0; i < 4; i++) {
        tf_host(kk[1].x, kk[1].y, 0u, i, &b1[i].x, &b1[i].y);
        tf_host(kk[2].x, kk[2].y, 0u, i, &b2[i].x, &b2[i].y);
    }
    Keys K;
    K.kth1 = kk[0]; K.kth2 = kk[3];
    K.r1 = b1[0]; K.c1 = b1[1]; K.m1 = b1[2]; K.s01 = b1[3];
    K.r2 = b2[0]; K.c2 = b2[1]; K.m2 = b2[2]; K.s02 = b2[3];

    k_rng  <<< (2499072 + 255)/256, 256 >>> (K, th1, th2, Rlf, Clf);
    k_pmac1<<< dim3(32, 4), 256 >>> (x);
    k_scan <<< 256, 512 >>> ();
    k_pmac2<<< dim3(32, 4, 3), 256 >>> ();
    k_epi  <<< dim3(32, 4), 256 >>> (out);
}

// round 10
// speedup vs baseline: 1.1109x; 1.0392x over previous
#include <cuda_runtime.h>
#include <stdint.h>

// ---------------- constants ----------------
#define EPSc   0.05f
#define DTc    0.1f
#define RMINc  1.0e5f
#define RMAXc  1.0e7f
#define CMINc  1.0e-7f
#define CMAXc  1.0e-4f

// ---------------- device scratch (static: no allocation allowed) ----------------
__device__ float g_w1p  [4*34*32];        // [n][m][o]   raw noisy theta1 (m=32 bias, m=33 zeros-row)
__device__ float g_w2p  [4*1058*64];      // [n][j][2*o] raw noisy theta2, duplicated + K-permuted
__device__ float g_a1T  [4*32*256*32];    // [n][c][t][b]
__device__ float g_beta [2*1024*4*256];   // [bank][k][n][t]   (TRANSPOSED for coalesced scan)
__device__ float g_s0   [2*1024*4*32];    // [bank][k][n][b]
__device__ float g_yout [4*1024*256*32];  // [n][k][t][b]   (128 MB)
__device__ float g_part [4*4*8192*32];    // [slice][n][m][o]  split-K partials (16.8 MB)

// ---------------- packed f32x2 FMA ----------------
#define FMA2(d, a, b, c) \
    asm("fma.rn.f32x2 %0, %1, %2, %3;" : "=l"(d) : "l"(a), "l"(b), "l"(c))

// ---------------- JAX threefry2x32 (partitionable semantics) ----------------
__device__ __forceinline__ uint2 tf2x32_d(uint32_t k0, uint32_t k1, uint32_t c0, uint32_t c1) {
    uint32_t ks2 = k0 ^ k1 ^ 0x1BD11BDAu;
    uint32_t x0 = c0 + k0, x1 = c1 + k1;
#define TFR(r) { x0 += x1; x1 = __funnelshift_l(x1, x1, (r)); x1 ^= x0; }
    TFR(13) TFR(15) TFR(26) TFR(6)   x0 += k1;  x1 += ks2 + 1u;
    TFR(17) TFR(29) TFR(16) TFR(24)  x0 += ks2; x1 += k0  + 2u;
    TFR(13) TFR(15) TFR(26) TFR(6)   x0 += k0;  x1 += k1  + 3u;
    TFR(17) TFR(29) TFR(16) TFR(24)  x0 += k1;  x1 += ks2 + 4u;
    TFR(13) TFR(15) TFR(26) TFR(6)   x0 += ks2; x1 += k0  + 5u;
#undef TFR
    return make_uint2(x0, x1);
}

__device__ __forceinline__ float u01p(uint2 key, uint32_t idx) {
    uint2 v = tf2x32_d(key.x, key.y, 0u, idx);
    uint32_t u = v.x ^ v.y;
    return __uint_as_float((u >> 9) | 0x3f800000u) - 1.0f;
}

struct Keys {
    uint2 kth1, kth2;          // theta noise keys
    uint2 r1, c1, m1;          // bank1 nR, nC, mu
    uint2 r2, c2, m2;          // bank2
    uint2 s01, s02;            // initial states
};

// ---------------- kernel: ALL RNG work in one launch ----------------
// ranges: [0,4352) thn1 | [4352,139776) thn2 | [139776,2236928) beta | rest s0
__global__ void __launch_bounds__(256) k_rng(Keys K, const float* __restrict__ th1,
                                             const float* __restrict__ th2,
                                             const float* __restrict__ Rlf,
                                             const float* __restrict__ Clf) {
    int gi = blockIdx.x * blockDim.x + threadIdx.x;
    if (gi < 4352) {
        // theta1 noise: shape (4, 34, 32), idx = (n*34+m)*32+o
        int i = gi;
        int o = i & 31; int nm = i >> 5; int m = nm % 34;
        float u = u01p(K.kth1, (uint32_t)i);
        float noise = (u * 2.0f - 1.0f) * EPSc + 1.0f;
        float t = th1[m*32 + o];
        t = fminf(fmaxf(t, -10.0f), 10.0f);
        if (fabsf(t) < 0.01f) t = 0.0f;
        g_w1p[i] = t * noise;                 // same [n][m][o] layout as idx
    } else if (gi < 139776) {
        // theta2 noise: shape (4, 1058, 32), idx = (n*1058+m)*32+o
        int i = gi - 4352;
        int o = i & 31; int nm = i >> 5; int m = nm % 1058; int n = nm / 1058;
        float u = u01p(K.kth2, (uint32_t)i);
        float noise = (u * 2.0f - 1.0f) * EPSc + 1.0f;
        float t = th2[m*32 + o];
        t = fminf(fmaxf(t, -10.0f), 10.0f);
        if (fabsf(t) < 0.01f) t = 0.0f;
        float v = t * noise;
        int j;
        if (m >= 1056) j = m;                 // 1056 bias, 1057 denom-only
        else {
            int c = m / 33, g = m % 33;
            j = (g == 0) ? (1024 + c) : (c*32 + g - 1);
        }
        g_w2p[(n*1058 + j)*64 + 2*o    ] = v;
        g_w2p[(n*1058 + j)*64 + 2*o + 1] = v;
    } else if (gi < 2236928) {
        // beta: per-bank RNG element idx e over logical shape (256 t,1024 k,4 n)
        // stored TRANSPOSED at [bank][k][n][t]
        int i = gi - 139776;
        int bank = i >> 20;
        uint32_t e = (uint32_t)(i & 1048575);
        int t  = (int)(e >> 12);
        int k  = (int)((e >> 2) & 1023u);
        int bn = (int)(e & 3u);
        uint2 kR = bank ? K.r2 : K.r1;
        uint2 kC = bank ? K.c2 : K.c1;
        uint2 km = bank ? K.m2 : K.m1;
        float nR = (u01p(kR, e) * 2.0f - 1.0f) * EPSc + 1.0f;
        float nC = (u01p(kC, e) * 2.0f - 1.0f) * EPSc + 1.0f;
        float mu =  u01p(km, e) * 0.2f + 1.0f;
        float Rr = Rlf[k*2 + bank], Cr = Clf[k*2 + bank];
        float Rt = (1.0f / (1.0f + expf(-Rr))) * (RMAXc - RMINc) + RMINc;
        float Ct = (1.0f / (1.0f + expf(-Cr))) * (CMAXc - CMINc) + CMINc;
        float RC = mu * (Rt * nR) * (Ct * nC);
        g_beta[bank*1048576 + (k*4 + bn)*256 + t] = RC / (RC + DTc);
    } else if (gi < 2499072) {
        // s0: shape (1024,4,32) per bank
        int i = gi - 2236928;
        int bank = i >> 17;
        uint32_t e = (uint32_t)(i & 131071);
        g_s0[i] = u01p(bank ? K.s02 : K.s01, e);
    }
}

// ---------------- kernel: pmac1 (x -> a1T), self-normalizing ----------------
// grid (32 t-chunks, 4 n), 256 threads = 8 t x 32 b
__global__ void __launch_bounds__(256) k_pmac1(const float* __restrict__ x) {
    int n = blockIdx.y;
    int tc = blockIdx.x;
    int tid = threadIdx.x;
    int tl = tid & 7, b = tid >> 3;
    int t = tc*8 + tl;
    __shared__ float w[34*32];
    __shared__ float invs[32];
    __shared__ float osm[8][8][33];
    for (int i = tid; i < 34*32; i += 256) w[i] = g_w1p[n*34*32 + i];
    __syncthreads();
    if (tid < 32) {
        float s = 0.0f;
        #pragma unroll
        for (int m = 0; m < 34; m++) s += fabsf(w[m*32 + tid]);
        invs[tid] = 1.0f / (s + 1e-10f);
    }
    __syncthreads();
    const float* xp = x + ((size_t)(n*32 + b)*32)*256 + t;
    float acc[32];
    const float4* wb4 = (const float4*)&w[32*32];       // raw bias row
    #pragma unroll
    for (int o4 = 0; o4 < 8; o4++) {
        float4 v = wb4[o4];
        acc[4*o4+0]=v.x; acc[4*o4+1]=v.y; acc[4*o4+2]=v.z; acc[4*o4+3]=v.w;
    }
    #pragma unroll 4
    for (int m = 0; m < 32; m++) {
        float xv = xp[(size_t)m*256];
        const float4* wr = (const float4*)&w[m*32];
        #pragma unroll
        for (int o4 = 0; o4 < 8; o4++) {
            float4 v = wr[o4];
            acc[4*o4+0]=fmaf(xv,v.x,acc[4*o4+0]); acc[4*o4+1]=fmaf(xv,v.y,acc[4*o4+1]);
            acc[4*o4+2]=fmaf(xv,v.z,acc[4*o4+2]); acc[4*o4+3]=fmaf(xv,v.w,acc[4*o4+3]);
        }
    }
    // activation + transposed (coalesced) store of a1T[n][o][t][b]
    for (int og = 0; og < 4; og++) {
        __syncthreads();
        #pragma unroll
        for (int oo = 0; oo < 8; oo++) {
            int o = og*8 + oo;
            osm[oo][tl][b] = 0.05f + 0.5f * tanhf((acc[o]*invs[o] - 0.3f) * 3.0f);
        }
        __syncthreads();
        int b_r = tid & 31, hi = tid >> 5;
        #pragma unroll
        for (int j = 0; j < 8; j++) {
            g_a1T[((size_t)(n*32 + og*8 + hi)*256 + tc*8 + j)*32 + b_r] = osm[hi][j][b_r];
        }
    }
}

// ---------------- kernel: fused two-bank scan ----------------
// grid 256 = (n 4, c 32, fh 2); 512 threads = 16 f x 32 b
// beta is [bank][k][n][t]: one coalesced 128B load per warp per 32 steps,
// broadcast through shfl.
__global__ void __launch_bounds__(512) k_scan() {
    int bi = blockIdx.x;
    int n = bi & 3, c = (bi >> 2) & 31, fh = bi >> 7;
    int lane = threadIdx.x & 31;
    int f = fh*16 + (threadIdx.x >> 5), b = lane;
    int k = c*32 + f;
    float s = g_s0[(k*4 + n)*32 + b];
    float r = g_s0[131072 + (k*4 + n)*32 + b];
    const float* xp  = &g_a1T[((size_t)(n*32 + c)*256) * 32 + b];   // +t*32
    const float* b1p = &g_beta[(k*4 + n)*256];                      // +t
    const float* b2p = b1p + 1048576;
    float* yp = &g_yout[((size_t)(n*1024 + k)*256) * 32 + b];       // +t*32
    for (int tt = 0; tt < 8; tt++) {
        float be1v = b1p[tt*32 + lane];       // coalesced: 32 consecutive t
        float be2v = b2p[tt*32 + lane];
        const float* xq = xp + tt*32*32;
        float*       yq = yp + tt*32*32;
        #pragma unroll 8
        for (int u = 0; u < 32; u++) {
            float be1 = __shfl_sync(0xffffffffu, be1v, u);
            float be2 = __shfl_sync(0xffffffffu, be2v, u);
            float xv  = xq[u*32];
            yq[u*32] = r;                      // scan emits the PRE-update carry
            r = be2 * r + (1.0f - be2) * s;    // bank2 consumes y1[t] = current s
            s = be1 * s + (1.0f - be1) * xv;   // bank1 update
        }
    }
}

// ---------------- kernel: pmac2 GEMM, split-K x 4 ----------------
// Per (n, slice): partial[m, o] over slice K-rows (272,272,272,240).
// Block: 256-row M tile, full N=32. Thread: 8 rows x 4 cols via 16 FFMA2/k.
// 2-stage cp.async pipeline, K-chunk 16. 3 blocks/SM target.
__global__ void __launch_bounds__(256, 3) k_pmac2() {
    const int n  = blockIdx.y;
    const int sl = blockIdx.z;               // K slice 0..3
    const int M0 = blockIdx.x * 256;
    const int j0 = sl * 272;
    const int nstages = (sl < 3) ? 17 : 15;
    const int tid = threadIdx.x;
    const int cg = tid & 7;        // col group: o = cg*4 + c
    const int rg = tid >> 3;       // row group: m = M0 + rg*8 + rr
    __shared__ float hs[2][16][256];
    __shared__ float wd[2][16][64];
    const float* ybase = g_yout + (size_t)n*1024*8192 + M0;   // + j*8192
    const float* abase = g_a1T  + (size_t)n*32*8192   + M0;   // + (j-1024)*8192
    const float* wbase = g_w2p  + (size_t)n*1058*64;          // + j*64

    unsigned long long acc[4][4];
    #pragma unroll
    for (int rp = 0; rp < 4; rp++)
        #pragma unroll
        for (int cc = 0; cc < 4; cc++) acc[rp][cc] = 0ull;

    auto load_stage = [&](int s, int buf) {
        int k0 = j0 + s * 16;
        #pragma unroll
        for (int j = 0; j < 4; j++) {
            int ch = tid + 256*j;
            int kk = ch >> 6, f4 = ch & 63;
            int jg = k0 + kk;
            const float* src = (jg < 1024)
                ? (ybase + (size_t)jg*8192 + f4*4)
                : (abase + (size_t)(jg - 1024)*8192 + f4*4);
            unsigned dst = (unsigned)__cvta_generic_to_shared(&hs[buf][kk][f4*4]);
            asm volatile("cp.async.cg.shared.global [%0], [%1], 16;" :: "r"(dst), "l"(src));
        }
        {
            int kk = tid >> 4, f4 = tid & 15;
            const float* src = wbase + (size_t)(k0 + kk)*64 + f4*4;
            unsigned dst = (unsigned)__cvta_generic_to_shared(&wd[buf][kk][f4*4]);
            asm volatile("cp.async.cg.shared.global [%0], [%1], 16;" :: "r"(dst), "l"(src));
        }
        asm volatile("cp.async.commit_group;");
    };

    load_stage(0, 0);
    for (int s = 0; s < nstages; s++) {
        int buf = s & 1;
        if (s < nstages - 1) { load_stage(s + 1, buf ^ 1); asm volatile("cp.async.wait_group 1;"); }
        else                 { asm volatile("cp.async.wait_group 0;"); }
        __syncthreads();
        #pragma unroll
        for (int kk = 0; kk < 16; kk++) {
            ulonglong2 hA = *(const ulonglong2*)(&hs[buf][kk][rg*8]);
            ulonglong2 hB = *(const ulonglong2*)(&hs[buf][kk][rg*8 + 4]);
            ulonglong2 wA = *(const ulonglong2*)(&wd[buf][kk][cg*8]);
            ulonglong2 wB = *(const ulonglong2*)(&wd[buf][kk][cg*8 + 4]);
            unsigned long long h[4]  = { hA.x, hA.y, hB.x, hB.y };
            unsigned long long wv[4] = { wA.x, wA.y, wB.x, wB.y };
            #pragma unroll
            for (int rp = 0; rp < 4; rp++) {
                #pragma unroll
                for (int cc = 0; cc < 4; cc++)
                    FMA2(acc[rp][cc], h[rp], wv[cc], acc[rp][cc]);
            }
        }
        __syncthreads();
    }

    // store partial sums: g_part[sl][n][m][o], float4 over cc (o = cg*4..cg*4+3)
    float* pbase = g_part + ((size_t)(sl*4 + n)*8192) * 32;
    #pragma unroll
    for (int rp = 0; rp < 4; rp++) {
        int m0 = M0 + rg*8 + rp*2;
        float4 lo4, hi4;
        float* l = (float*)&lo4; float* h = (float*)&hi4;
        #pragma unroll
        for (int cc = 0; cc < 4; cc++) {
            l[cc] = __uint_as_float((unsigned)(acc[rp][cc] & 0xffffffffu));
            h[cc] = __uint_as_float((unsigned)(acc[rp][cc] >> 32));
        }
        *(float4*)(pbase + (size_t)m0*32       + cg*4) = lo4;
        *(float4*)(pbase + (size_t)(m0 + 1)*32 + cg*4) = hi4;
    }
}

// ---------------- kernel: epilogue (sum partials + bias, norm, act, store) ----
// grid (32 t-chunks, 4 n), 256 threads.
__global__ void __launch_bounds__(256) k_epi(float* __restrict__ out) {
    const int n  = blockIdx.y;
    const int tc = blockIdx.x;           // 8 t values per block
    const int tid = threadIdx.x;
    __shared__ float res[8][32][33];     // [t_local][b][o] (pad 33)
    __shared__ float psum[8][32];
    __shared__ float inv_sm[32], bias_sm[32];
    const float* wbase = g_w2p + (size_t)n*1058*64;

    // per-column denominator (sum |w| over all 1058 rows) + bias
    {
        int o = tid & 31, p = tid >> 5;
        float s = 0.0f;
        for (int j = p; j < 1058; j += 8) s += fabsf(wbase[(size_t)j*64 + 2*o]);
        psum[p][o] = s;
    }
    __syncthreads();
    if (tid < 32) {
        float s = 0.0f;
        #pragma unroll
        for (int p = 0; p < 8; p++) s += psum[p][tid];
        inv_sm[tid] = 1.0f / (s + 1e-10f);
        bias_sm[tid] = wbase[(size_t)1056*64 + 2*tid];
    }
    __syncthreads();

    const float* p0 = g_part + ((size_t)(0*4 + n)*8192 + tc*256) * 32;
    const float* p1 = g_part + ((size_t)(1*4 + n)*8192 + tc*256) * 32;
    const float* p2 = g_part + ((size_t)(2*4 + n)*8192 + tc*256) * 32;
    const float* p3 = g_part + ((size_t)(3*4 + n)*8192 + tc*256) * 32;
    for (int i = tid; i < 8192; i += 256) {
        int ml = i >> 5, o = i & 31;
        float z = ((p0[i] + p1[i]) + (p2[i] + p3[i])) + bias_sm[o];
        res[ml >> 5][ml & 31][o] = 0.05f + 0.5f * tanhf((z*inv_sm[o] - 0.3f) * 3.0f);
    }
    __syncthreads();

    // write out[n][b][o][t]: each thread owns 4 (b,o) pairs, 8 t each (2 float4)
    #pragma unroll
    for (int q = 0; q < 4; q++) {
        int pair = tid + q*256;          // 0..1023 = b*32+o
        int b = pair >> 5, o = pair & 31;
        float4 v0, v1;
        float* v = (float*)&v0;
        #pragma unroll
        for (int j = 0; j < 4; j++) v[j] = res[j][b][o];
        v = (float*)&v1;
        #pragma unroll
        for (int j = 0; j < 4; j++) v[j] = res[4 + j][b][o];
        float* op = out + ((size_t)(n*32 + b)*32 + o)*256 + tc*8;
        *(float4*)op       = v0;
        *(float4*)(op + 4) = v1;
    }
}

// ---------------- host threefry (derive subkeys) ----------------
static inline uint32_t rotl32(uint32_t x, int r) { return (x << r) | (x >> (32 - r)); }
static void tf_host(uint32_t k0, uint32_t k1, uint32_t c0, uint32_t c1,
                    uint32_t* o0, uint32_t* o1) {
    uint32_t ks[3] = { k0, k1, k0 ^ k1 ^ 0x1BD11BDAu };
    const int R[2][4] = { {13,15,26,6}, {17,29,16,24} };
    uint32_t x0 = c0 + k0, x1 = c1 + k1;
    for (int i = 0; i < 5; i++) {
        for (int j = 0; j < 4; j++) { x0 += x1; x1 = rotl32(x1, R[i & 1][j]); x1 ^= x0; }
        x0 += ks[(i + 1) % 3];
        x1 += ks[(i + 2) % 3] + (uint32_t)(i + 1);
    }
    *o0 = x0; *o1 = x1;
}

extern "C" void kernel_launch(void* const* d_in, const int* in_sizes, int n_in,
                              void* d_out, int out_size) {
    const float* x   = (const float*)d_in[0];
    const float* th1 = (const float*)d_in[1];
    const float* th2 = (const float*)d_in[2];
    const float* Rlf = (const float*)d_in[3];
    const float* Clf = (const float*)d_in[4];
    float* out = (float*)d_out;

    // key(42) = (0,42); split(key,4) -> k1..k4 (partitionable)
    uint2 kk[4];
    for (uint32_t i = 0; i < 4; i++) tf_host(0u, 42u, 0u, i, &kk[i].x, &kk[i].y);
    uint2 b1[4], b2[4];
    for (uint32_t i = 0; i < 4; i++) {
        tf_host(kk[1].x, kk[1].y, 0u, i, &b1[i].x, &b1[i].y);
        tf_host(kk[2].x, kk[2].y, 0u, i, &b2[i].x, &b2[i].y);
    }
    Keys K;
    K.kth1 = kk[0]; K.kth2 = kk[3];
    K.r1 = b1[0]; K.c1 = b1[1]; K.m1 = b1[2]; K.s01 = b1[3];
    K.r2 = b2[0]; K.c2 = b2[1]; K.m2 = b2[2]; K.s02 = b2[3];

    k_rng  <<< (2499072 + 255)/256, 256 >>> (K, th1, th2, Rlf, Clf);
    k_pmac1<<< dim3(32, 4), 256 >>> (x);
    k_scan <<< 256, 512 >>> ();
    k_pmac2<<< dim3(32, 4, 4), 256 >>> ();
    k_epi  <<< dim3(32, 4), 256 >>> (out);
}

// round 15
// speedup vs baseline: 1.4905x; 1.3418x over previous
#include <cuda_runtime.h>
#include <cuda_bf16.h>
#include <stdint.h>

// ---------------- constants ----------------
#define EPSc   0.05f
#define DTc    0.1f
#define RMINc  1.0e5f
#define RMAXc  1.0e7f
#define CMINc  1.0e-7f
#define CMAXc  1.0e-4f

// ---------------- device scratch (static: no allocation allowed) ----------------
__device__ float g_w1p  [4*34*32];        // [n][m][o]   raw noisy theta1 (m=32 bias, m=33 zeros)
__device__ float g_w2p  [4*1058*32];      // [n][j][o]   raw noisy theta2, K-permuted (no dup)
__device__ float g_a1T  [4*32*256*32];    // [n][c][t][b]  fp32 (scan input)
__device__ __nv_bfloat16 g_a1H [4*32*256*32];   // bf16 copy for pmac2
__device__ float g_beta [2*1024*4*256];   // [bank][k][n][t]   (transposed for coalesced scan)
__device__ float g_s0   [2*1024*4*32];    // [bank][k][n][b]
__device__ __nv_bfloat16 g_youtH[4*1024*256*32]; // [n][k][t][b]  bf16 (64 MB)
__device__ float g_part [4*4*8192*32];    // [slice][n][m][o]  split-K partials

// ---------------- packed f32x2 FMA + pack helpers ----------------
#define FMA2(d, a, b, c) \
    asm("fma.rn.f32x2 %0, %1, %2, %3;" : "=l"(d) : "l"(a), "l"(b), "l"(c))

__device__ __forceinline__ unsigned long long pack2(uint32_t lo, uint32_t hi) {
    unsigned long long d;
    asm("mov.b64 %0, {%1, %2};" : "=l"(d) : "r"(lo), "r"(hi));
    return d;
}
__device__ __forceinline__ unsigned long long packff(float v) {
    unsigned long long d;
    asm("mov.b64 %0, {%1, %1};" : "=l"(d) : "f"(v));
    return d;
}
// bf16x2 (two rows) -> f32x2 operand
__device__ __forceinline__ unsigned long long bf2f2(uint32_t r) {
    return pack2(r << 16, r & 0xffff0000u);
}

// ---------------- JAX threefry2x32 (partitionable semantics) ----------------
__device__ __forceinline__ uint2 tf2x32_d(uint32_t k0, uint32_t k1, uint32_t c0, uint32_t c1) {
    uint32_t ks2 = k0 ^ k1 ^ 0x1BD11BDAu;
    uint32_t x0 = c0 + k0, x1 = c1 + k1;
#define TFR(r) { x0 += x1; x1 = __funnelshift_l(x1, x1, (r)); x1 ^= x0; }
    TFR(13) TFR(15) TFR(26) TFR(6)   x0 += k1;  x1 += ks2 + 1u;
    TFR(17) TFR(29) TFR(16) TFR(24)  x0 += ks2; x1 += k0  + 2u;
    TFR(13) TFR(15) TFR(26) TFR(6)   x0 += k0;  x1 += k1  + 3u;
    TFR(17) TFR(29) TFR(16) TFR(24)  x0 += k1;  x1 += ks2 + 4u;
    TFR(13) TFR(15) TFR(26) TFR(6)   x0 += ks2; x1 += k0  + 5u;
#undef TFR
    return make_uint2(x0, x1);
}

__device__ __forceinline__ float u01p(uint2 key, uint32_t idx) {
    uint2 v = tf2x32_d(key.x, key.y, 0u, idx);
    uint32_t u = v.x ^ v.y;
    return __uint_as_float((u >> 9) | 0x3f800000u) - 1.0f;
}

struct Keys {
    uint2 kth1, kth2;
    uint2 r1, c1, m1;
    uint2 r2, c2, m2;
    uint2 s01, s02;
};

// ---------------- kernel: ALL RNG work in one launch ----------------
__global__ void __launch_bounds__(256) k_rng(Keys K, const float* __restrict__ th1,
                                             const float* __restrict__ th2,
                                             const float* __restrict__ Rlf,
                                             const float* __restrict__ Clf) {
    int gi = blockIdx.x * blockDim.x + threadIdx.x;
    if (gi < 4352) {
        int i = gi;
        int o = i & 31; int nm = i >> 5; int m = nm % 34;
        float u = u01p(K.kth1, (uint32_t)i);
        float noise = (u * 2.0f - 1.0f) * EPSc + 1.0f;
        float t = th1[m*32 + o];
        t = fminf(fmaxf(t, -10.0f), 10.0f);
        if (fabsf(t) < 0.01f) t = 0.0f;
        g_w1p[i] = t * noise;
    } else if (gi < 139776) {
        int i = gi - 4352;
        int o = i & 31; int nm = i >> 5; int m = nm % 1058; int n = nm / 1058;
        float u = u01p(K.kth2, (uint32_t)i);
        float noise = (u * 2.0f - 1.0f) * EPSc + 1.0f;
        float t = th2[m*32 + o];
        t = fminf(fmaxf(t, -10.0f), 10.0f);
        if (fabsf(t) < 0.01f) t = 0.0f;
        float v = t * noise;
        int j;
        if (m >= 1056) j = m;                 // 1056 bias, 1057 denom-only
        else {
            int c = m / 33, g = m % 33;
            j = (g == 0) ? (1024 + c) : (c*32 + g - 1);
        }
        g_w2p[(n*1058 + j)*32 + o] = v;
    } else if (gi < 2236928) {
        int i = gi - 139776;
        int bank = i >> 20;
        uint32_t e = (uint32_t)(i & 1048575);
        int t  = (int)(e >> 12);
        int k  = (int)((e >> 2) & 1023u);
        int bn = (int)(e & 3u);
        uint2 kR = bank ? K.r2 : K.r1;
        uint2 kC = bank ? K.c2 : K.c1;
        uint2 km = bank ? K.m2 : K.m1;
        float nR = (u01p(kR, e) * 2.0f - 1.0f) * EPSc + 1.0f;
        float nC = (u01p(kC, e) * 2.0f - 1.0f) * EPSc + 1.0f;
        float mu =  u01p(km, e) * 0.2f + 1.0f;
        float Rr = Rlf[k*2 + bank], Cr = Clf[k*2 + bank];
        float Rt = (1.0f / (1.0f + expf(-Rr))) * (RMAXc - RMINc) + RMINc;
        float Ct = (1.0f / (1.0f + expf(-Cr))) * (CMAXc - CMINc) + CMINc;
        float RC = mu * (Rt * nR) * (Ct * nC);
        g_beta[bank*1048576 + (k*4 + bn)*256 + t] = RC / (RC + DTc);
    } else if (gi < 2499072) {
        int i = gi - 2236928;
        int bank = i >> 17;
        uint32_t e = (uint32_t)(i & 131071);
        g_s0[i] = u01p(bank ? K.s02 : K.s01, e);
    }
}

// ---------------- kernel: pmac1 (x -> a1T fp32 + a1H bf16), self-normalizing --
__global__ void __launch_bounds__(256) k_pmac1(const float* __restrict__ x) {
    int n = blockIdx.y;
    int tc = blockIdx.x;
    int tid = threadIdx.x;
    int tl = tid & 7, b = tid >> 3;
    int t = tc*8 + tl;
    __shared__ float w[34*32];
    __shared__ float invs[32];
    __shared__ float osm[8][8][33];
    for (int i = tid; i < 34*32; i += 256) w[i] = g_w1p[n*34*32 + i];
    __syncthreads();
    if (tid < 32) {
        float s = 0.0f;
        #pragma unroll
        for (int m = 0; m < 34; m++) s += fabsf(w[m*32 + tid]);
        invs[tid] = 1.0f / (s + 1e-10f);
    }
    __syncthreads();
    const float* xp = x + ((size_t)(n*32 + b)*32)*256 + t;
    float acc[32];
    const float4* wb4 = (const float4*)&w[32*32];
    #pragma unroll
    for (int o4 = 0; o4 < 8; o4++) {
        float4 v = wb4[o4];
        acc[4*o4+0]=v.x; acc[4*o4+1]=v.y; acc[4*o4+2]=v.z; acc[4*o4+3]=v.w;
    }
    #pragma unroll 4
    for (int m = 0; m < 32; m++) {
        float xv = xp[(size_t)m*256];
        const float4* wr = (const float4*)&w[m*32];
        #pragma unroll
        for (int o4 = 0; o4 < 8; o4++) {
            float4 v = wr[o4];
            acc[4*o4+0]=fmaf(xv,v.x,acc[4*o4+0]); acc[4*o4+1]=fmaf(xv,v.y,acc[4*o4+1]);
            acc[4*o4+2]=fmaf(xv,v.z,acc[4*o4+2]); acc[4*o4+3]=fmaf(xv,v.w,acc[4*o4+3]);
        }
    }
    for (int og = 0; og < 4; og++) {
        __syncthreads();
        #pragma unroll
        for (int oo = 0; oo < 8; oo++) {
            int o = og*8 + oo;
            osm[oo][tl][b] = 0.05f + 0.5f * tanhf((acc[o]*invs[o] - 0.3f) * 3.0f);
        }
        __syncthreads();
        int b_r = tid & 31, hi = tid >> 5;
        #pragma unroll
        for (int j = 0; j < 8; j++) {
            float v = osm[hi][j][b_r];
            size_t idx = ((size_t)(n*32 + og*8 + hi)*256 + tc*8 + j)*32 + b_r;
            g_a1T[idx] = v;
            g_a1H[idx] = __float2bfloat16_rn(v);
        }
    }
}

// ---------------- kernel: fused two-bank scan (bf16 output) ----------------
// grid 256 = (n 4, c 32, fh 2); 512 threads = 16 f x 32 b
__global__ void __launch_bounds__(512) k_scan() {
    int bi = blockIdx.x;
    int n = bi & 3, c = (bi >> 2) & 31, fh = bi >> 7;
    int lane = threadIdx.x & 31;
    int f = fh*16 + (threadIdx.x >> 5), b = lane;
    int k = c*32 + f;
    float s = g_s0[(k*4 + n)*32 + b];
    float r = g_s0[131072 + (k*4 + n)*32 + b];
    const float* xp  = &g_a1T[((size_t)(n*32 + c)*256) * 32 + b];   // +t*32
    const float* b1p = &g_beta[(k*4 + n)*256];                      // +t
    const float* b2p = b1p + 1048576;
    __nv_bfloat16* yp = &g_youtH[((size_t)(n*1024 + k)*256) * 32 + b];
    for (int tt = 0; tt < 8; tt++) {
        float be1v = b1p[tt*32 + lane];
        float be2v = b2p[tt*32 + lane];
        const float* xq = xp + tt*32*32;
        __nv_bfloat16* yq = yp + tt*32*32;
        #pragma unroll 8
        for (int u = 0; u < 32; u++) {
            float be1 = __shfl_sync(0xffffffffu, be1v, u);
            float be2 = __shfl_sync(0xffffffffu, be2v, u);
            float xv  = xq[u*32];
            yq[u*32] = __float2bfloat16_rn(r);     // PRE-update carry
            r = be2 * r + (1.0f - be2) * s;
            s = be1 * s + (1.0f - be1) * xv;
        }
    }
}

// ---------------- kernel: pmac2 GEMM, split-K x 4, bf16 h ----------------
// Block: 256-row M tile, full N=32. Thread: 8 rows x 4 cols via 16 FFMA2/k.
// Inner loop: 1 LDS.128 (8 bf16 h rows) + 1 LDS.128 (4 f32 w) per k.
__global__ void __launch_bounds__(256, 3) k_pmac2() {
    const int n  = blockIdx.y;
    const int sl = blockIdx.z;               // K slice 0..3
    const int M0 = blockIdx.x * 256;
    const int j0 = sl * 272;
    const int nstages = (sl < 3) ? 17 : 15;
    const int tid = threadIdx.x;
    const int cg = tid & 7;        // col group: o = cg*4 + c
    const int rg = tid >> 3;       // row group: m = M0 + rg*8 + rr
    __shared__ __nv_bfloat16 hs[2][16][256];   // 16 KB
    __shared__ float wd[2][16][32];            //  4 KB
    const __nv_bfloat16* ybase = g_youtH + (size_t)n*1024*8192 + M0;  // + j*8192
    const __nv_bfloat16* abase = g_a1H   + (size_t)n*32*8192   + M0;  // + (j-1024)*8192
    const float* wbase = g_w2p + (size_t)n*1058*32;                    // + j*32

    unsigned long long acc[4][4];
    #pragma unroll
    for (int rp = 0; rp < 4; rp++)
        #pragma unroll
        for (int cc = 0; cc < 4; cc++) acc[rp][cc] = 0ull;

    auto load_stage = [&](int s, int buf) {
        int k0 = j0 + s * 16;
        // h: 16 rows x 512B = 8 KB = 512 chunks of 16B
        #pragma unroll
        for (int j = 0; j < 2; j++) {
            int ch = tid + 256*j;
            int kk = ch >> 5, c8 = ch & 31;
            int jg = k0 + kk;
            const __nv_bfloat16* src = (jg < 1024)
                ? (ybase + (size_t)jg*8192 + c8*8)
                : (abase + (size_t)(jg - 1024)*8192 + c8*8);
            unsigned dst = (unsigned)__cvta_generic_to_shared(&hs[buf][kk][c8*8]);
            asm volatile("cp.async.cg.shared.global [%0], [%1], 16;" :: "r"(dst), "l"(src));
        }
        // w: 16 rows x 128B = 2 KB = 128 chunks of 16B
        if (tid < 128) {
            int kk = tid >> 3, f4 = tid & 7;
            const float* src = wbase + (size_t)(k0 + kk)*32 + f4*4;
            unsigned dst = (unsigned)__cvta_generic_to_shared(&wd[buf][kk][f4*4]);
            asm volatile("cp.async.cg.shared.global [%0], [%1], 16;" :: "r"(dst), "l"(src));
        }
        asm volatile("cp.async.commit_group;");
    };

    load_stage(0, 0);
    for (int s = 0; s < nstages; s++) {
        int buf = s & 1;
        if (s < nstages - 1) { load_stage(s + 1, buf ^ 1); asm volatile("cp.async.wait_group 1;"); }
        else                 { asm volatile("cp.async.wait_group 0;"); }
        __syncthreads();
        #pragma unroll
        for (int kk = 0; kk < 16; kk++) {
            uint4  hraw = *(const uint4*)(&hs[buf][kk][rg*8]);   // 8 bf16 rows
            float4 wv4  = *(const float4*)(&wd[buf][kk][cg*4]);  // 4 w cols
            unsigned long long h[4] = { bf2f2(hraw.x), bf2f2(hraw.y),
                                        bf2f2(hraw.z), bf2f2(hraw.w) };
            unsigned long long wv[4] = { packff(wv4.x), packff(wv4.y),
                                         packff(wv4.z), packff(wv4.w) };
            #pragma unroll
            for (int rp = 0; rp < 4; rp++) {
                #pragma unroll
                for (int cc = 0; cc < 4; cc++)
                    FMA2(acc[rp][cc], h[rp], wv[cc], acc[rp][cc]);
            }
        }
        __syncthreads();
    }

    float* pbase = g_part + ((size_t)(sl*4 + n)*8192) * 32;
    #pragma unroll
    for (int rp = 0; rp < 4; rp++) {
        int m0 = M0 + rg*8 + rp*2;
        float4 lo4, hi4;
        float* l = (float*)&lo4; float* h = (float*)&hi4;
        #pragma unroll
        for (int cc = 0; cc < 4; cc++) {
            l[cc] = __uint_as_float((unsigned)(acc[rp][cc] & 0xffffffffu));
            h[cc] = __uint_as_float((unsigned)(acc[rp][cc] >> 32));
        }
        *(float4*)(pbase + (size_t)m0*32       + cg*4) = lo4;
        *(float4*)(pbase + (size_t)(m0 + 1)*32 + cg*4) = hi4;
    }
}

// ---------------- kernel: epilogue (sum partials + bias, norm, act, store) ----
__global__ void __launch_bounds__(256) k_epi(float* __restrict__ out) {
    const int n  = blockIdx.y;
    const int tc = blockIdx.x;
    const int tid = threadIdx.x;
    __shared__ float res[8][32][33];
    __shared__ float psum[8][32];
    __shared__ float inv_sm[32], bias_sm[32];
    const float* wbase = g_w2p + (size_t)n*1058*32;

    {
        int o = tid & 31, p = tid >> 5;
        float s = 0.0f;
        for (int j = p; j < 1058; j += 8) s += fabsf(wbase[(size_t)j*32 + o]);
        psum[p][o] = s;
    }
    __syncthreads();
    if (tid < 32) {
        float s = 0.0f;
        #pragma unroll
        for (int p = 0; p < 8; p++) s += psum[p][tid];
        inv_sm[tid] = 1.0f / (s + 1e-10f);
        bias_sm[tid] = wbase[(size_t)1056*32 + tid];
    }
    __syncthreads();

    const float* p0 = g_part + ((size_t)(0*4 + n)*8192 + tc*256) * 32;
    const float* p1 = g_part + ((size_t)(1*4 + n)*8192 + tc*256) * 32;
    const float* p2 = g_part + ((size_t)(2*4 + n)*8192 + tc*256) * 32;
    const float* p3 = g_part + ((size_t)(3*4 + n)*8192 + tc*256) * 32;
    for (int i = tid; i < 8192; i += 256) {
        int ml = i >> 5, o = i & 31;
        float z = ((p0[i] + p1[i]) + (p2[i] + p3[i])) + bias_sm[o];
        res[ml >> 5][ml & 31][o] = 0.05f + 0.5f * tanhf((z*inv_sm[o] - 0.3f) * 3.0f);
    }
    __syncthreads();

    #pragma unroll
    for (int q = 0; q < 4; q++) {
        int pair = tid + q*256;
        int b = pair >> 5, o = pair & 31;
        float4 v0, v1;
        float* v = (float*)&v0;
        #pragma unroll
        for (int j = 0; j < 4; j++) v[j] = res[j][b][o];
        v = (float*)&v1;
        #pragma unroll
        for (int j = 0; j < 4; j++) v[j] = res[4 + j][b][o];
        float* op = out + ((size_t)(n*32 + b)*32 + o)*256 + tc*8;
        *(float4*)op       = v0;
        *(float4*)(op + 4) = v1;
    }
}

// ---------------- host threefry (derive subkeys) ----------------
static inline uint32_t rotl32(uint32_t x, int r) { return (x << r) | (x >> (32 - r)); }
static void tf_host(uint32_t k0, uint32_t k1, uint32_t c0, uint32_t c1,
                    uint32_t* o0, uint32_t* o1) {
    uint32_t ks[3] = { k0, k1, k0 ^ k1 ^ 0x1BD11BDAu };
    const int R[2][4] = { {13,15,26,6}, {17,29,16,24} };
    uint32_t x0 = c0 + k0, x1 = c1 + k1;
    for (int i = 0; i < 5; i++) {
        for (int j = 0; j < 4; j++) { x0 += x1; x1 = rotl32(x1, R[i & 1][j]); x1 ^= x0; }
        x0 += ks[(i + 1) % 3];
        x1 += ks[(i + 2) % 3] + (uint32_t)(i + 1);
    }
    *o0 = x0; *o1 = x1;
}

extern "C" void kernel_launch(void* const* d_in, const int* in_sizes, int n_in,
                              void* d_out, int out_size) {
    const float* x   = (const float*)d_in[0];
    const float* th1 = (const float*)d_in[1];
    const float* th2 = (const float*)d_in[2];
    const float* Rlf = (const float*)d_in[3];
    const float* Clf = (const float*)d_in[4];
    float* out = (float*)d_out;

    uint2 kk[4];
    for (uint32_t i = 0; i < 4; i++) tf_host(0u, 42u, 0u, i, &kk[i].x, &kk[i].y);
    uint2 b1[4], b2[4];
    for (uint32_t i = 0; i < 4; i++) {
        tf_host(kk[1].x, kk[1].y, 0u, i, &b1[i].x, &b1[i].y);
        tf_host(kk[2].x, kk[2].y, 0u, i, &b2[i].x, &b2[i].y);
    }
    Keys K;
    K.kth1 = kk[0]; K.kth2 = kk[3];
    K.r1 = b1[0]; K.c1 = b1[1]; K.m1 = b1[2]; K.s01 = b1[3];
    K.r2 = b2[0]; K.c2 = b2[1]; K.m2 = b2[2]; K.s02 = b2[3];

    k_rng  <<< (2499072 + 255)/256, 256 >>> (K, th1, th2, Rlf, Clf);
    k_pmac1<<< dim3(32, 4), 256 >>> (x);
    k_scan <<< 256, 512 >>> ();
    k_pmac2<<< dim3(32, 4, 4), 256 >>> ();
    k_epi  <<< dim3(32, 4), 256 >>> (out);
}

// round 16
// speedup vs baseline: 1.8564x; 1.2455x over previous
#include <cuda_runtime.h>
#include <cuda_bf16.h>
#include <stdint.h>

// ---------------- constants ----------------
#define EPSc   0.05f
#define DTc    0.1f
#define RMINc  1.0e5f
#define RMAXc  1.0e7f
#define CMINc  1.0e-7f
#define CMAXc  1.0e-4f

// ---------------- device scratch (static: no allocation allowed) ----------------
__device__ float g_w1p  [4*34*32];        // [n][m][o]   raw noisy theta1
__device__ float g_w2p  [4*1058*32];      // [n][j][o]   raw noisy theta2, K-permuted (fp32, for epi)
__device__ __nv_bfloat16 g_w2pT[4*32*1072]; // [n][o][j]  bf16 transposed (for MMA B), padded stride
__device__ float g_a1T  [4*32*256*32];    // [n][c][t][b]  fp32 (scan input)
__device__ __nv_bfloat16 g_a1H [4*32*256*32];   // bf16 copy for pmac2
__device__ float g_beta [2*1024*4*256];   // [bank][k][n][t]
__device__ float g_s0   [2*1024*4*32];    // [bank][k][n][b]
__device__ __nv_bfloat16 g_youtH[4*1024*256*32]; // [n][k][t][b]  bf16 (64 MB)
__device__ float g_part [4*4*8192*32];    // [slice][n][m][o]  split-K partials

__device__ __forceinline__ uint32_t smem_u32(const void* p) {
    return (uint32_t)__cvta_generic_to_shared(p);
}

// ---------------- JAX threefry2x32 (partitionable semantics) ----------------
__device__ __forceinline__ uint2 tf2x32_d(uint32_t k0, uint32_t k1, uint32_t c0, uint32_t c1) {
    uint32_t ks2 = k0 ^ k1 ^ 0x1BD11BDAu;
    uint32_t x0 = c0 + k0, x1 = c1 + k1;
#define TFR(r) { x0 += x1; x1 = __funnelshift_l(x1, x1, (r)); x1 ^= x0; }
    TFR(13) TFR(15) TFR(26) TFR(6)   x0 += k1;  x1 += ks2 + 1u;
    TFR(17) TFR(29) TFR(16) TFR(24)  x0 += ks2; x1 += k0  + 2u;
    TFR(13) TFR(15) TFR(26) TFR(6)   x0 += k0;  x1 += k1  + 3u;
    TFR(17) TFR(29) TFR(16) TFR(24)  x0 += k1;  x1 += ks2 + 4u;
    TFR(13) TFR(15) TFR(26) TFR(6)   x0 += ks2; x1 += k0  + 5u;
#undef TFR
    return make_uint2(x0, x1);
}

__device__ __forceinline__ float u01p(uint2 key, uint32_t idx) {
    uint2 v = tf2x32_d(key.x, key.y, 0u, idx);
    uint32_t u = v.x ^ v.y;
    return __uint_as_float((u >> 9) | 0x3f800000u) - 1.0f;
}

struct Keys {
    uint2 kth1, kth2;
    uint2 r1, c1, m1;
    uint2 r2, c2, m2;
    uint2 s01, s02;
};

// ---------------- kernel: ALL RNG work in one launch ----------------
__global__ void __launch_bounds__(256) k_rng(Keys K, const float* __restrict__ th1,
                                             const float* __restrict__ th2,
                                             const float* __restrict__ Rlf,
                                             const float* __restrict__ Clf) {
    int gi = blockIdx.x * blockDim.x + threadIdx.x;
    if (gi < 4352) {
        int i = gi;
        int o = i & 31; int nm = i >> 5; int m = nm % 34;
        float u = u01p(K.kth1, (uint32_t)i);
        float noise = (u * 2.0f - 1.0f) * EPSc + 1.0f;
        float t = th1[m*32 + o];
        t = fminf(fmaxf(t, -10.0f), 10.0f);
        if (fabsf(t) < 0.01f) t = 0.0f;
        g_w1p[i] = t * noise;
    } else if (gi < 139776) {
        int i = gi - 4352;
        int o = i & 31; int nm = i >> 5; int m = nm % 1058; int n = nm / 1058;
        float u = u01p(K.kth2, (uint32_t)i);
        float noise = (u * 2.0f - 1.0f) * EPSc + 1.0f;
        float t = th2[m*32 + o];
        t = fminf(fmaxf(t, -10.0f), 10.0f);
        if (fabsf(t) < 0.01f) t = 0.0f;
        float v = t * noise;
        int j;
        if (m >= 1056) j = m;                 // 1056 bias, 1057 denom-only
        else {
            int c = m / 33, g = m % 33;
            j = (g == 0) ? (1024 + c) : (c*32 + g - 1);
        }
        g_w2p[(n*1058 + j)*32 + o] = v;
        if (j < 1056) g_w2pT[(n*32 + o)*1072 + j] = __float2bfloat16_rn(v);
    } else if (gi < 2236928) {
        int i = gi - 139776;
        int bank = i >> 20;
        uint32_t e = (uint32_t)(i & 1048575);
        int t  = (int)(e >> 12);
        int k  = (int)((e >> 2) & 1023u);
        int bn = (int)(e & 3u);
        uint2 kR = bank ? K.r2 : K.r1;
        uint2 kC = bank ? K.c2 : K.c1;
        uint2 km = bank ? K.m2 : K.m1;
        float nR = (u01p(kR, e) * 2.0f - 1.0f) * EPSc + 1.0f;
        float nC = (u01p(kC, e) * 2.0f - 1.0f) * EPSc + 1.0f;
        float mu =  u01p(km, e) * 0.2f + 1.0f;
        float Rr = Rlf[k*2 + bank], Cr = Clf[k*2 + bank];
        float Rt = (1.0f / (1.0f + expf(-Rr))) * (RMAXc - RMINc) + RMINc;
        float Ct = (1.0f / (1.0f + expf(-Cr))) * (CMAXc - CMINc) + CMINc;
        float RC = mu * (Rt * nR) * (Ct * nC);
        g_beta[bank*1048576 + (k*4 + bn)*256 + t] = RC / (RC + DTc);
    } else if (gi < 2499072) {
        int i = gi - 2236928;
        int bank = i >> 17;
        uint32_t e = (uint32_t)(i & 131071);
        g_s0[i] = u01p(bank ? K.s02 : K.s01, e);
    }
}

// ---------------- kernel: pmac1 (x -> a1T fp32 + a1H bf16), self-normalizing --
__global__ void __launch_bounds__(256) k_pmac1(const float* __restrict__ x) {
    int n = blockIdx.y;
    int tc = blockIdx.x;
    int tid = threadIdx.x;
    int tl = tid & 7, b = tid >> 3;
    int t = tc*8 + tl;
    __shared__ float w[34*32];
    __shared__ float invs[32];
    __shared__ float osm[8][8][33];
    for (int i = tid; i < 34*32; i += 256) w[i] = g_w1p[n*34*32 + i];
    __syncthreads();
    if (tid < 32) {
        float s = 0.0f;
        #pragma unroll
        for (int m = 0; m < 34; m++) s += fabsf(w[m*32 + tid]);
        invs[tid] = 1.0f / (s + 1e-10f);
    }
    __syncthreads();
    const float* xp = x + ((size_t)(n*32 + b)*32)*256 + t;
    float acc[32];
    const float4* wb4 = (const float4*)&w[32*32];
    #pragma unroll
    for (int o4 = 0; o4 < 8; o4++) {
        float4 v = wb4[o4];
        acc[4*o4+0]=v.x; acc[4*o4+1]=v.y; acc[4*o4+2]=v.z; acc[4*o4+3]=v.w;
    }
    #pragma unroll 4
    for (int m = 0; m < 32; m++) {
        float xv = xp[(size_t)m*256];
        const float4* wr = (const float4*)&w[m*32];
        #pragma unroll
        for (int o4 = 0; o4 < 8; o4++) {
            float4 v = wr[o4];
            acc[4*o4+0]=fmaf(xv,v.x,acc[4*o4+0]); acc[4*o4+1]=fmaf(xv,v.y,acc[4*o4+1]);
            acc[4*o4+2]=fmaf(xv,v.z,acc[4*o4+2]); acc[4*o4+3]=fmaf(xv,v.w,acc[4*o4+3]);
        }
    }
    for (int og = 0; og < 4; og++) {
        __syncthreads();
        #pragma unroll
        for (int oo = 0; oo < 8; oo++) {
            int o = og*8 + oo;
            osm[oo][tl][b] = 0.05f + 0.5f * tanhf((acc[o]*invs[o] - 0.3f) * 3.0f);
        }
        __syncthreads();
        int b_r = tid & 31, hi = tid >> 5;
        #pragma unroll
        for (int j = 0; j < 8; j++) {
            float v = osm[hi][j][b_r];
            size_t idx = ((size_t)(n*32 + og*8 + hi)*256 + tc*8 + j)*32 + b_r;
            g_a1T[idx] = v;
            g_a1H[idx] = __float2bfloat16_rn(v);
        }
    }
}

// ---------------- kernel: fused two-bank scan (bf16 output) ----------------
__global__ void __launch_bounds__(512) k_scan() {
    int bi = blockIdx.x;
    int n = bi & 3, c = (bi >> 2) & 31, fh = bi >> 7;
    int lane = threadIdx.x & 31;
    int f = fh*16 + (threadIdx.x >> 5), b = lane;
    int k = c*32 + f;
    float s = g_s0[(k*4 + n)*32 + b];
    float r = g_s0[131072 + (k*4 + n)*32 + b];
    const float* xp  = &g_a1T[((size_t)(n*32 + c)*256) * 32 + b];
    const float* b1p = &g_beta[(k*4 + n)*256];
    const float* b2p = b1p + 1048576;
    __nv_bfloat16* yp = &g_youtH[((size_t)(n*1024 + k)*256) * 32 + b];
    for (int tt = 0; tt < 8; tt++) {
        float be1v = b1p[tt*32 + lane];
        float be2v = b2p[tt*32 + lane];
        const float* xq = xp + tt*32*32;
        __nv_bfloat16* yq = yp + tt*32*32;
        #pragma unroll 8
        for (int u = 0; u < 32; u++) {
            float be1 = __shfl_sync(0xffffffffu, be1v, u);
            float be2 = __shfl_sync(0xffffffffu, be2v, u);
            float xv  = xq[u*32];
            yq[u*32] = __float2bfloat16_rn(r);     // PRE-update carry
            r = be2 * r + (1.0f - be2) * s;
            s = be1 * s + (1.0f - be1) * xv;
        }
    }
}

// ---------------- kernel: pmac2 GEMM via mma.sync (bf16), split-K x 4 ----------
// Per (n, slice): partial[256-row M tile, 32 o] over slice K-rows.
// Warp tile m64 x n16; per k16: 4 ldmatrix.x4.trans (A) + 4 LDS.32 (B) + 8 MMA.
__global__ void __launch_bounds__(256, 3) k_pmac2() {
    const int n  = blockIdx.y;
    const int sl = blockIdx.z;               // K slice 0..3
    const int M0 = blockIdx.x * 256;
    const int j0 = sl * 272;
    const int nstages = (sl < 3) ? 17 : 15;
    const int tid = threadIdx.x;
    const int wid = tid >> 5, lane = tid & 31;
    const int wm0 = (wid >> 1) * 64;         // warp m offset within M tile
    const int wn0 = (wid & 1) * 16;          // warp n offset
    __shared__ __nv_bfloat16 hs[2][16][264]; // padded: 528B row stride (bank-shift 4 words)
    __shared__ __nv_bfloat16 wt[2][32][24];  // padded: 48B row stride
    const __nv_bfloat16* ybase = g_youtH + (size_t)n*1024*8192 + M0;
    const __nv_bfloat16* abase = g_a1H   + (size_t)n*32*8192   + M0;
    const __nv_bfloat16* wtb   = g_w2pT  + (size_t)n*32*1072;

    float acc[4][2][4];
    #pragma unroll
    for (int mi = 0; mi < 4; mi++)
        #pragma unroll
        for (int ni = 0; ni < 2; ni++)
            #pragma unroll
            for (int q = 0; q < 4; q++) acc[mi][ni][q] = 0.0f;

    auto load_stage = [&](int s, int buf) {
        int k0 = j0 + s * 16;
        #pragma unroll
        for (int j = 0; j < 2; j++) {
            int ch = tid + 256*j;
            int kk = ch >> 5, c8 = ch & 31;
            int jg = k0 + kk;
            const __nv_bfloat16* src = (jg < 1024)
                ? (ybase + (size_t)jg*8192 + c8*8)
                : (abase + (size_t)(jg - 1024)*8192 + c8*8);
            uint32_t dst = smem_u32(&hs[buf][kk][c8*8]);
            asm volatile("cp.async.cg.shared.global [%0], [%1], 16;" :: "r"(dst), "l"(src));
        }
        if (tid < 64) {
            int o = tid >> 1, half = tid & 1;
            const __nv_bfloat16* src = wtb + (size_t)o*1072 + k0 + half*8;
            uint32_t dst = smem_u32(&wt[buf][o][half*8]);
            asm volatile("cp.async.cg.shared.global [%0], [%1], 16;" :: "r"(dst), "l"(src));
        }
        asm volatile("cp.async.commit_group;");
    };

    // ldmatrix source-row selector (A^T storage -> .trans)
    const int krow = ((lane >> 4) << 3) + (lane & 7);
    const int msel = ((lane >> 3) & 1) * 8;

    load_stage(0, 0);
    for (int s = 0; s < nstages; s++) {
        int buf = s & 1;
        if (s < nstages - 1) { load_stage(s + 1, buf ^ 1); asm volatile("cp.async.wait_group 1;"); }
        else                 { asm volatile("cp.async.wait_group 0;"); }
        __syncthreads();

        // B fragments (k16 x n8 per ni)
        uint32_t b0[2], b1[2];
        #pragma unroll
        for (int ni = 0; ni < 2; ni++) {
            const __nv_bfloat16* wp = &wt[buf][wn0 + ni*8 + (lane >> 2)][2*(lane & 3)];
            b0[ni] = *(const uint32_t*)wp;
            b1[ni] = *(const uint32_t*)(wp + 8);
        }
        #pragma unroll
        for (int mi = 0; mi < 4; mi++) {
            uint32_t a0, a1, a2, a3;
            uint32_t sa = smem_u32(&hs[buf][krow][wm0 + mi*16 + msel]);
            asm volatile("ldmatrix.sync.aligned.m8n8.x4.trans.shared.b16 {%0,%1,%2,%3}, [%4];"
                         : "=r"(a0), "=r"(a1), "=r"(a2), "=r"(a3) : "r"(sa));
            #pragma unroll
            for (int ni = 0; ni < 2; ni++) {
                asm volatile(
                    "mma.sync.aligned.m16n8k16.row.col.f32.bf16.bf16.f32 "
                    "{%0,%1,%2,%3}, {%4,%5,%6,%7}, {%8,%9}, {%0,%1,%2,%3};"
                    : "+f"(acc[mi][ni][0]), "+f"(acc[mi][ni][1]),
                      "+f"(acc[mi][ni][2]), "+f"(acc[mi][ni][3])
                    : "r"(a0), "r"(a1), "r"(a2), "r"(a3), "r"(b0[ni]), "r"(b1[ni]));
            }
        }
        __syncthreads();
    }

    // store partials: D fragment row = lane>>2 (+8), col = 2*(lane&3) (+1)
    float* pbase = g_part + ((size_t)(sl*4 + n)*8192) * 32;
    #pragma unroll
    for (int mi = 0; mi < 4; mi++) {
        int m = M0 + wm0 + mi*16 + (lane >> 2);
        #pragma unroll
        for (int ni = 0; ni < 2; ni++) {
            int o = wn0 + ni*8 + 2*(lane & 3);
            float2 vlo = make_float2(acc[mi][ni][0], acc[mi][ni][1]);
            float2 vhi = make_float2(acc[mi][ni][2], acc[mi][ni][3]);
            *(float2*)(pbase + (size_t)m*32 + o)       = vlo;
            *(float2*)(pbase + (size_t)(m + 8)*32 + o) = vhi;
        }
    }
}

// ---------------- kernel: epilogue (sum partials + bias, norm, act, store) ----
__global__ void __launch_bounds__(256) k_epi(float* __restrict__ out) {
    const int n  = blockIdx.y;
    const int tc = blockIdx.x;
    const int tid = threadIdx.x;
    __shared__ float res[8][32][33];
    __shared__ float psum[8][32];
    __shared__ float inv_sm[32], bias_sm[32];
    const float* wbase = g_w2p + (size_t)n*1058*32;

    {
        int o = tid & 31, p = tid >> 5;
        float s = 0.0f;
        for (int j = p; j < 1058; j += 8) s += fabsf(wbase[(size_t)j*32 + o]);
        psum[p][o] = s;
    }
    __syncthreads();
    if (tid < 32) {
        float s = 0.0f;
        #pragma unroll
        for (int p = 0; p < 8; p++) s += psum[p][tid];
        inv_sm[tid] = 1.0f / (s + 1e-10f);
        bias_sm[tid] = wbase[(size_t)1056*32 + tid];
    }
    __syncthreads();

    const float* p0 = g_part + ((size_t)(0*4 + n)*8192 + tc*256) * 32;
    const float* p1 = g_part + ((size_t)(1*4 + n)*8192 + tc*256) * 32;
    const float* p2 = g_part + ((size_t)(2*4 + n)*8192 + tc*256) * 32;
    const float* p3 = g_part + ((size_t)(3*4 + n)*8192 + tc*256) * 32;
    for (int i = tid; i < 8192; i += 256) {
        int ml = i >> 5, o = i & 31;
        float z = ((p0[i] + p1[i]) + (p2[i] + p3[i])) + bias_sm[o];
        res[ml >> 5][ml & 31][o] = 0.05f + 0.5f * tanhf((z*inv_sm[o] - 0.3f) * 3.0f);
    }
    __syncthreads();

    #pragma unroll
    for (int q = 0; q < 4; q++) {
        int pair = tid + q*256;
        int b = pair >> 5, o = pair & 31;
        float4 v0, v1;
        float* v = (float*)&v0;
        #pragma unroll
        for (int j = 0; j < 4; j++) v[j] = res[j][b][o];
        v = (float*)&v1;
        #pragma unroll
        for (int j = 0; j < 4; j++) v[j] = res[4 + j][b][o];
        float* op = out + ((size_t)(n*32 + b)*32 + o)*256 + tc*8;
        *(float4*)op       = v0;
        *(float4*)(op + 4) = v1;
    }
}

// ---------------- host threefry (derive subkeys) ----------------
static inline uint32_t rotl32(uint32_t x, int r) { return (x << r) | (x >> (32 - r)); }
static void tf_host(uint32_t k0, uint32_t k1, uint32_t c0, uint32_t c1,
                    uint32_t* o0, uint32_t* o1) {
    uint32_t ks[3] = { k0, k1, k0 ^ k1 ^ 0x1BD11BDAu };
    const int R[2][4] = { {13,15,26,6}, {17,29,16,24} };
    uint32_t x0 = c0 + k0, x1 = c1 + k1;
    for (int i = 0; i < 5; i++) {
        for (int j = 0; j < 4; j++) { x0 += x1; x1 = rotl32(x1, R[i & 1][j]); x1 ^= x0; }
        x0 += ks[(i + 1) % 3];
        x1 += ks[(i + 2) % 3] + (uint32_t)(i + 1);
    }
    *o0 = x0; *o1 = x1;
}

extern "C" void kernel_launch(void* const* d_in, const int* in_sizes, int n_in,
                              void* d_out, int out_size) {
    const float* x   = (const float*)d_in[0];
    const float* th1 = (const float*)d_in[1];
    const float* th2 = (const float*)d_in[2];
    const float* Rlf = (const float*)d_in[3];
    const float* Clf = (const float*)d_in[4];
    float* out = (float*)d_out;

    uint2 kk[4];
    for (uint32_t i = 0; i < 4; i++) tf_host(0u, 42u, 0u, i, &kk[i].x, &kk[i].y);
    uint2 b1[4], b2[4];
    for (uint32_t i = 0; i < 4; i++) {
        tf_host(kk[1].x, kk[1].y, 0u, i, &b1[i].x, &b1[i].y);
        tf_host(kk[2].x, kk[2].y, 0u, i, &b2[i].x, &b2[i].y);
    }
    Keys K;
    K.kth1 = kk[0]; K.kth2 = kk[3];
    K.r1 = b1[0]; K.c1 = b1[1]; K.m1 = b1[2]; K.s01 = b1[3];
    K.r2 = b2[0]; K.c2 = b2[1]; K.m2 = b2[2]; K.s02 = b2[3];

    k_rng  <<< (2499072 + 255)/256, 256 >>> (K, th1, th2, Rlf, Clf);
    k_pmac1<<< dim3(32, 4), 256 >>> (x);
    k_scan <<< 256, 512 >>> ();
    k_pmac2<<< dim3(32, 4, 4), 256 >>> ();
    k_epi  <<< dim3(32, 4), 256 >>> (out);
}